// round 4
// baseline (speedup 1.0000x reference)
#include <cuda_runtime.h>
#include <cuda_bf16.h>
#include <math.h>

// Problem constants
#define BATCH 4
#define SEQ 4096
#define DMODEL 1024
#define DK 256
#define MROWS (BATCH * SEQ)   // 16384

// ---------------- scratch (projections) ----------------
__device__ float g_q[(size_t)MROWS * DK];
__device__ float g_k[(size_t)MROWS * DK];
__device__ float g_v[(size_t)MROWS * DK];

// ---------------- projection GEMM ----------------
// C[m,n] = sum_k X[m,k] * W[n,k] + b[n]
// X: [MROWS, DMODEL], W: [DK, DMODEL], C: [MROWS, DK]
// Tile: BM=64, BN=64, BK=16; 256 threads; 4x4 strided micro-tile.
#define PBM 64
#define PBN 64
#define PBK 16

__global__ __launch_bounds__(256) void proj_kernel(
    const float* __restrict__ Xq, const float* __restrict__ Xk, const float* __restrict__ Xv,
    const float* __restrict__ Wq, const float* __restrict__ bq,
    const float* __restrict__ Wk, const float* __restrict__ bk,
    const float* __restrict__ Wv, const float* __restrict__ bv)
{
    const float* X; const float* W; const float* bias; float* C;
    int z = blockIdx.z;
    if (z == 0)      { X = Xq; W = Wq; bias = bq; C = g_q; }
    else if (z == 1) { X = Xk; W = Wk; bias = bk; C = g_k; }
    else             { X = Xv; W = Wv; bias = bv; C = g_v; }

    // k-major transposed tiles, pad 65 to break store conflicts
    __shared__ float As[PBK][65];
    __shared__ float Bs[PBK][65];

    int tid = threadIdx.x;
    int tx = tid & 15;        // col group
    int ty = tid >> 4;        // row group
    int m0 = blockIdx.y * PBM;
    int n0 = blockIdx.x * PBN;

    // loader mapping: each thread loads one float4 of A and one of B per k-tile
    int lrow = tid >> 2;            // 0..63
    int lc   = (tid & 3) << 2;      // 0,4,8,12

    const float* Xp = X + (size_t)(m0 + lrow) * DMODEL + lc;
    const float* Wp = W + (size_t)(n0 + lrow) * DMODEL + lc;

    float acc[4][4];
    #pragma unroll
    for (int i = 0; i < 4; i++)
        #pragma unroll
        for (int j = 0; j < 4; j++) acc[i][j] = 0.0f;

    for (int k0 = 0; k0 < DMODEL; k0 += PBK) {
        float4 a4 = *(const float4*)(Xp + k0);
        float4 b4 = *(const float4*)(Wp + k0);
        __syncthreads();
        As[lc + 0][lrow] = a4.x; As[lc + 1][lrow] = a4.y;
        As[lc + 2][lrow] = a4.z; As[lc + 3][lrow] = a4.w;
        Bs[lc + 0][lrow] = b4.x; Bs[lc + 1][lrow] = b4.y;
        Bs[lc + 2][lrow] = b4.z; Bs[lc + 3][lrow] = b4.w;
        __syncthreads();
        #pragma unroll
        for (int k = 0; k < PBK; k++) {
            float a[4], b[4];
            #pragma unroll
            for (int i = 0; i < 4; i++) a[i] = As[k][ty + 16 * i];
            #pragma unroll
            for (int j = 0; j < 4; j++) b[j] = Bs[k][tx + 16 * j];
            #pragma unroll
            for (int i = 0; i < 4; i++)
                #pragma unroll
                for (int j = 0; j < 4; j++)
                    acc[i][j] += a[i] * b[j];
        }
    }

    float bb[4];
    #pragma unroll
    for (int j = 0; j < 4; j++) bb[j] = bias[n0 + tx + 16 * j];

    #pragma unroll
    for (int i = 0; i < 4; i++) {
        size_t row = (size_t)(m0 + ty + 16 * i) * DK + n0;
        #pragma unroll
        for (int j = 0; j < 4; j++)
            C[row + tx + 16 * j] = acc[i][j] + bb[j];
    }
}

// ---------------- flash attention ----------------
// One CTA: 64 query rows of one batch, streams K/V in 64-row tiles.
// smem: Qs[256][65] (k-major), Ks[256][65] (k-major), Vs[64][256], Ps[64][65]
#define BQ 64
#define BKV 64

#define QS_OFF 0
#define KS_OFF (256 * 65)
#define VS_OFF (KS_OFF + 256 * 65)
#define PS_OFF (VS_OFF + 64 * 256)
#define SMEM_FLOATS (PS_OFF + 64 * 65)
#define SMEM_BYTES (SMEM_FLOATS * 4)

__global__ __launch_bounds__(256, 1) void attn_kernel(float* __restrict__ Out)
{
    int b  = blockIdx.y;
    int q0 = blockIdx.x * BQ;

    extern __shared__ float sm[];
    float* Qs = sm + QS_OFF;
    float* Ks = sm + KS_OFF;
    float* Vs = sm + VS_OFF;
    float* Ps = sm + PS_OFF;

    const float* Qg = g_q + (size_t)b * SEQ * DK;
    const float* Kg = g_k + (size_t)b * SEQ * DK;
    const float* Vg = g_v + (size_t)b * SEQ * DK;

    int tid = threadIdx.x;
    int tx = tid & 15;
    int ty = tid >> 4;

    // ---- load Q tile transposed: Qs[k][q] ----
    #pragma unroll
    for (int it = 0; it < 16; it++) {
        int idx4 = tid + it * 256;
        int r = idx4 >> 6;        // query row 0..63
        int g = idx4 & 63;        // float4 group in D
        float4 v = *(const float4*)(Qg + (size_t)(q0 + r) * DK + g * 4);
        Qs[(4 * g + 0) * 65 + r] = v.x;
        Qs[(4 * g + 1) * 65 + r] = v.y;
        Qs[(4 * g + 2) * 65 + r] = v.z;
        Qs[(4 * g + 3) * 65 + r] = v.w;
    }

    float m_i[4], l_i[4];
    float o[4][16];
    #pragma unroll
    for (int i = 0; i < 4; i++) {
        m_i[i] = -INFINITY; l_i[i] = 0.0f;
        #pragma unroll
        for (int c = 0; c < 16; c++) o[i][c] = 0.0f;
    }

    const float scale = 0.0625f;  // 1/sqrt(256)

    for (int s0 = 0; s0 < SEQ; s0 += BKV) {
        __syncthreads();  // previous PV done before overwriting Ks/Vs
        // ---- load K transposed, V direct ----
        #pragma unroll
        for (int it = 0; it < 16; it++) {
            int idx4 = tid + it * 256;
            int r = idx4 >> 6;
            int g = idx4 & 63;
            float4 kv = *(const float4*)(Kg + (size_t)(s0 + r) * DK + g * 4);
            Ks[(4 * g + 0) * 65 + r] = kv.x;
            Ks[(4 * g + 1) * 65 + r] = kv.y;
            Ks[(4 * g + 2) * 65 + r] = kv.z;
            Ks[(4 * g + 3) * 65 + r] = kv.w;
            float4 vv = *(const float4*)(Vg + (size_t)(s0 + r) * DK + g * 4);
            *(float4*)(Vs + r * 256 + g * 4) = vv;
        }
        __syncthreads();

        // ---- scores S = Q K^T * scale (64x64 tile, 4x4/thread strided) ----
        float acc[4][4];
        #pragma unroll
        for (int i = 0; i < 4; i++)
            #pragma unroll
            for (int j = 0; j < 4; j++) acc[i][j] = 0.0f;

        #pragma unroll 4
        for (int k = 0; k < DK; k++) {
            float a[4], bv[4];
            #pragma unroll
            for (int i = 0; i < 4; i++) a[i]  = Qs[k * 65 + ty + 16 * i];
            #pragma unroll
            for (int j = 0; j < 4; j++) bv[j] = Ks[k * 65 + tx + 16 * j];
            #pragma unroll
            for (int i = 0; i < 4; i++)
                #pragma unroll
                for (int j = 0; j < 4; j++)
                    acc[i][j] += a[i] * bv[j];
        }

        #pragma unroll
        for (int i = 0; i < 4; i++)
            #pragma unroll
            for (int j = 0; j < 4; j++) acc[i][j] *= scale;

        // ---- online softmax ----
        float mnew[4], corr[4], rs[4];
        #pragma unroll
        for (int i = 0; i < 4; i++) {
            float r = acc[i][0];
            r = fmaxf(r, acc[i][1]); r = fmaxf(r, acc[i][2]); r = fmaxf(r, acc[i][3]);
            #pragma unroll
            for (int off = 1; off < 16; off <<= 1)
                r = fmaxf(r, __shfl_xor_sync(0xffffffffu, r, off));
            mnew[i] = fmaxf(m_i[i], r);
            corr[i] = __expf(m_i[i] - mnew[i]);
            m_i[i] = mnew[i];
        }
        #pragma unroll
        for (int i = 0; i < 4; i++) {
            float s = 0.0f;
            #pragma unroll
            for (int j = 0; j < 4; j++) {
                float p = __expf(acc[i][j] - mnew[i]);
                Ps[(ty + 16 * i) * 65 + tx + 16 * j] = p;
                s += p;
            }
            #pragma unroll
            for (int off = 1; off < 16; off <<= 1)
                s += __shfl_xor_sync(0xffffffffu, s, off);
            rs[i] = s;
        }
        #pragma unroll
        for (int i = 0; i < 4; i++) {
            l_i[i] = l_i[i] * corr[i] + rs[i];
            #pragma unroll
            for (int c = 0; c < 16; c++) o[i][c] *= corr[i];
        }
        __syncthreads();

        // ---- PV: O += P @ V ----
        #pragma unroll 2
        for (int s = 0; s < BKV; s++) {
            float p0 = Ps[(ty +  0) * 65 + s];
            float p1 = Ps[(ty + 16) * 65 + s];
            float p2 = Ps[(ty + 32) * 65 + s];
            float p3 = Ps[(ty + 48) * 65 + s];
            #pragma unroll
            for (int c = 0; c < 16; c++) {
                float vv = Vs[s * 256 + c * 16 + tx];
                o[0][c] += p0 * vv;
                o[1][c] += p1 * vv;
                o[2][c] += p2 * vv;
                o[3][c] += p3 * vv;
            }
        }
    }

    // ---- epilogue ----
    #pragma unroll
    for (int i = 0; i < 4; i++) {
        float invl = 1.0f / l_i[i];
        size_t row = ((size_t)b * SEQ + q0 + ty + 16 * i) * DK;
        #pragma unroll
        for (int c = 0; c < 16; c++)
            Out[row + c * 16 + tx] = o[i][c] * invl;
    }
}

// ---------------- launch ----------------
extern "C" void kernel_launch(void* const* d_in, const int* in_sizes, int n_in,
                              void* d_out, int out_size)
{
    const float* xq = (const float*)d_in[0];
    const float* xk = (const float*)d_in[1];
    const float* xv = (const float*)d_in[2];
    // d_in[3] = mask (unused by reference forward)
    const float* Wq = (const float*)d_in[4];
    const float* bq = (const float*)d_in[5];
    const float* Wk = (const float*)d_in[6];
    const float* bk = (const float*)d_in[7];
    const float* Wv = (const float*)d_in[8];
    const float* bv = (const float*)d_in[9];
    float* out = (float*)d_out;

    cudaFuncSetAttribute(attn_kernel, cudaFuncAttributeMaxDynamicSharedMemorySize, SMEM_BYTES);

    dim3 pg(DK / PBN, MROWS / PBM, 3);
    proj_kernel<<<pg, 256>>>(xq, xk, xv, Wq, bq, Wk, bk, Wv, bv);

    dim3 ag(SEQ / BQ, BATCH);
    attn_kernel<<<ag, 256, SMEM_BYTES>>>(out);
}

// round 5
// speedup vs baseline: 1.0563x; 1.0563x over previous
#include <cuda_runtime.h>
#include <cuda_bf16.h>
#include <math.h>

// Problem constants
#define BATCH 4
#define SEQ 4096
#define DMODEL 1024
#define DK 256
#define MROWS (BATCH * SEQ)   // 16384

// ---------------- scratch (projections) ----------------
__device__ float g_q[(size_t)MROWS * DK];
__device__ float g_k[(size_t)MROWS * DK];
__device__ float g_v[(size_t)MROWS * DK];

// ---------------- projection GEMM ----------------
// C[m,n] = sum_k X[m,k] * W[n,k] + b[n]
// X: [MROWS, DMODEL], W: [DK, DMODEL], C: [MROWS, DK]
// Tile: BM=64, BN=64, BK=16; 256 threads; 4x4 strided micro-tile.
#define PBM 64
#define PBN 64
#define PBK 16

__global__ __launch_bounds__(256) void proj_kernel(
    const float* __restrict__ Xq, const float* __restrict__ Xk, const float* __restrict__ Xv,
    const float* __restrict__ Wq, const float* __restrict__ bq,
    const float* __restrict__ Wk, const float* __restrict__ bk,
    const float* __restrict__ Wv, const float* __restrict__ bv)
{
    const float* X; const float* W; const float* bias; float* C;
    int z = blockIdx.z;
    if (z == 0)      { X = Xq; W = Wq; bias = bq; C = g_q; }
    else if (z == 1) { X = Xk; W = Wk; bias = bk; C = g_k; }
    else             { X = Xv; W = Wv; bias = bv; C = g_v; }

    // k-major transposed tiles, pad 65 to break store conflicts
    __shared__ float As[PBK][65];
    __shared__ float Bs[PBK][65];

    int tid = threadIdx.x;
    int tx = tid & 15;        // col group
    int ty = tid >> 4;        // row group
    int m0 = blockIdx.y * PBM;
    int n0 = blockIdx.x * PBN;

    // loader mapping: each thread loads one float4 of A and one of B per k-tile
    int lrow = tid >> 2;            // 0..63
    int lc   = (tid & 3) << 2;      // 0,4,8,12

    const float* Xp = X + (size_t)(m0 + lrow) * DMODEL + lc;
    const float* Wp = W + (size_t)(n0 + lrow) * DMODEL + lc;

    float acc[4][4];
    #pragma unroll
    for (int i = 0; i < 4; i++)
        #pragma unroll
        for (int j = 0; j < 4; j++) acc[i][j] = 0.0f;

    for (int k0 = 0; k0 < DMODEL; k0 += PBK) {
        float4 a4 = *(const float4*)(Xp + k0);
        float4 b4 = *(const float4*)(Wp + k0);
        __syncthreads();
        As[lc + 0][lrow] = a4.x; As[lc + 1][lrow] = a4.y;
        As[lc + 2][lrow] = a4.z; As[lc + 3][lrow] = a4.w;
        Bs[lc + 0][lrow] = b4.x; Bs[lc + 1][lrow] = b4.y;
        Bs[lc + 2][lrow] = b4.z; Bs[lc + 3][lrow] = b4.w;
        __syncthreads();
        #pragma unroll
        for (int k = 0; k < PBK; k++) {
            float a[4], b[4];
            #pragma unroll
            for (int i = 0; i < 4; i++) a[i] = As[k][ty + 16 * i];
            #pragma unroll
            for (int j = 0; j < 4; j++) b[j] = Bs[k][tx + 16 * j];
            #pragma unroll
            for (int i = 0; i < 4; i++)
                #pragma unroll
                for (int j = 0; j < 4; j++)
                    acc[i][j] += a[i] * b[j];
        }
    }

    float bb[4];
    #pragma unroll
    for (int j = 0; j < 4; j++) bb[j] = bias[n0 + tx + 16 * j];

    #pragma unroll
    for (int i = 0; i < 4; i++) {
        size_t row = (size_t)(m0 + ty + 16 * i) * DK + n0;
        #pragma unroll
        for (int j = 0; j < 4; j++)
            C[row + tx + 16 * j] = acc[i][j] + bb[j];
    }
}

// ---------------- flash attention ----------------
// One CTA: 64 query rows of one batch, streams K/V in 64-row tiles.
// smem: Qs[256][65] (k-major), Ks[256][65] (k-major), Vs[64][256], Ps[64][65]
#define BQ 64
#define BKV 64

#define QS_OFF 0
#define KS_OFF (256 * 65)
#define VS_OFF (KS_OFF + 256 * 65)
#define PS_OFF (VS_OFF + 64 * 256)
#define SMEM_FLOATS (PS_OFF + 64 * 65)
#define SMEM_BYTES (SMEM_FLOATS * 4)

__global__ __launch_bounds__(256, 1) void attn_kernel(float* __restrict__ Out)
{
    int b  = blockIdx.y;
    int q0 = blockIdx.x * BQ;

    extern __shared__ float sm[];
    float* Qs = sm + QS_OFF;
    float* Ks = sm + KS_OFF;
    float* Vs = sm + VS_OFF;
    float* Ps = sm + PS_OFF;

    const float* Qg = g_q + (size_t)b * SEQ * DK;
    const float* Kg = g_k + (size_t)b * SEQ * DK;
    const float* Vg = g_v + (size_t)b * SEQ * DK;

    int tid = threadIdx.x;
    int tx = tid & 15;
    int ty = tid >> 4;

    // ---- load Q tile transposed: Qs[k][q] ----
    #pragma unroll
    for (int it = 0; it < 16; it++) {
        int idx4 = tid + it * 256;
        int r = idx4 >> 6;        // query row 0..63
        int g = idx4 & 63;        // float4 group in D
        float4 v = *(const float4*)(Qg + (size_t)(q0 + r) * DK + g * 4);
        Qs[(4 * g + 0) * 65 + r] = v.x;
        Qs[(4 * g + 1) * 65 + r] = v.y;
        Qs[(4 * g + 2) * 65 + r] = v.z;
        Qs[(4 * g + 3) * 65 + r] = v.w;
    }

    float m_i[4], l_i[4];
    float o[4][16];
    #pragma unroll
    for (int i = 0; i < 4; i++) {
        m_i[i] = -INFINITY; l_i[i] = 0.0f;
        #pragma unroll
        for (int c = 0; c < 16; c++) o[i][c] = 0.0f;
    }

    const float scale = 0.0625f;  // 1/sqrt(256)

    for (int s0 = 0; s0 < SEQ; s0 += BKV) {
        __syncthreads();  // previous PV done before overwriting Ks/Vs
        // ---- load K transposed, V direct ----
        #pragma unroll
        for (int it = 0; it < 16; it++) {
            int idx4 = tid + it * 256;
            int r = idx4 >> 6;
            int g = idx4 & 63;
            float4 kv = *(const float4*)(Kg + (size_t)(s0 + r) * DK + g * 4);
            Ks[(4 * g + 0) * 65 + r] = kv.x;
            Ks[(4 * g + 1) * 65 + r] = kv.y;
            Ks[(4 * g + 2) * 65 + r] = kv.z;
            Ks[(4 * g + 3) * 65 + r] = kv.w;
            float4 vv = *(const float4*)(Vg + (size_t)(s0 + r) * DK + g * 4);
            *(float4*)(Vs + r * 256 + g * 4) = vv;
        }
        __syncthreads();

        // ---- scores S = Q K^T * scale (64x64 tile, 4x4/thread strided) ----
        float acc[4][4];
        #pragma unroll
        for (int i = 0; i < 4; i++)
            #pragma unroll
            for (int j = 0; j < 4; j++) acc[i][j] = 0.0f;

        #pragma unroll 4
        for (int k = 0; k < DK; k++) {
            float a[4], bv[4];
            #pragma unroll
            for (int i = 0; i < 4; i++) a[i]  = Qs[k * 65 + ty + 16 * i];
            #pragma unroll
            for (int j = 0; j < 4; j++) bv[j] = Ks[k * 65 + tx + 16 * j];
            #pragma unroll
            for (int i = 0; i < 4; i++)
                #pragma unroll
                for (int j = 0; j < 4; j++)
                    acc[i][j] += a[i] * bv[j];
        }

        #pragma unroll
        for (int i = 0; i < 4; i++)
            #pragma unroll
            for (int j = 0; j < 4; j++) acc[i][j] *= scale;

        // ---- online softmax ----
        float mnew[4], corr[4], rs[4];
        #pragma unroll
        for (int i = 0; i < 4; i++) {
            float r = acc[i][0];
            r = fmaxf(r, acc[i][1]); r = fmaxf(r, acc[i][2]); r = fmaxf(r, acc[i][3]);
            #pragma unroll
            for (int off = 1; off < 16; off <<= 1)
                r = fmaxf(r, __shfl_xor_sync(0xffffffffu, r, off));
            mnew[i] = fmaxf(m_i[i], r);
            corr[i] = __expf(m_i[i] - mnew[i]);
            m_i[i] = mnew[i];
        }
        #pragma unroll
        for (int i = 0; i < 4; i++) {
            float s = 0.0f;
            #pragma unroll
            for (int j = 0; j < 4; j++) {
                float p = __expf(acc[i][j] - mnew[i]);
                Ps[(ty + 16 * i) * 65 + tx + 16 * j] = p;
                s += p;
            }
            #pragma unroll
            for (int off = 1; off < 16; off <<= 1)
                s += __shfl_xor_sync(0xffffffffu, s, off);
            rs[i] = s;
        }
        #pragma unroll
        for (int i = 0; i < 4; i++) {
            l_i[i] = l_i[i] * corr[i] + rs[i];
            #pragma unroll
            for (int c = 0; c < 16; c++) o[i][c] *= corr[i];
        }
        __syncthreads();

        // ---- PV: O += P @ V ----
        #pragma unroll 2
        for (int s = 0; s < BKV; s++) {
            float p0 = Ps[(ty +  0) * 65 + s];
            float p1 = Ps[(ty + 16) * 65 + s];
            float p2 = Ps[(ty + 32) * 65 + s];
            float p3 = Ps[(ty + 48) * 65 + s];
            #pragma unroll
            for (int c = 0; c < 16; c++) {
                float vv = Vs[s * 256 + c * 16 + tx];
                o[0][c] += p0 * vv;
                o[1][c] += p1 * vv;
                o[2][c] += p2 * vv;
                o[3][c] += p3 * vv;
            }
        }
    }

    // ---- epilogue ----
    #pragma unroll
    for (int i = 0; i < 4; i++) {
        float invl = 1.0f / l_i[i];
        size_t row = ((size_t)b * SEQ + q0 + ty + 16 * i) * DK;
        #pragma unroll
        for (int c = 0; c < 16; c++)
            Out[row + c * 16 + tx] = o[i][c] * invl;
    }
}

// ---------------- launch ----------------
extern "C" void kernel_launch(void* const* d_in, const int* in_sizes, int n_in,
                              void* d_out, int out_size)
{
    const float* xq = (const float*)d_in[0];
    const float* xk = (const float*)d_in[1];
    const float* xv = (const float*)d_in[2];
    // d_in[3] = mask (unused by reference forward)
    const float* Wq = (const float*)d_in[4];
    const float* bq = (const float*)d_in[5];
    const float* Wk = (const float*)d_in[6];
    const float* bk = (const float*)d_in[7];
    const float* Wv = (const float*)d_in[8];
    const float* bv = (const float*)d_in[9];
    float* out = (float*)d_out;

    cudaFuncSetAttribute(attn_kernel, cudaFuncAttributeMaxDynamicSharedMemorySize, SMEM_BYTES);

    dim3 pg(DK / PBN, MROWS / PBM, 3);
    proj_kernel<<<pg, 256>>>(xq, xk, xv, Wq, bq, Wk, bk, Wv, bv);

    dim3 ag(SEQ / BQ, BATCH);
    attn_kernel<<<ag, 256, SMEM_BYTES>>>(out);
}

// round 7
// speedup vs baseline: 1.5180x; 1.4371x over previous
#include <cuda_runtime.h>
#include <cuda_bf16.h>
#include <mma.h>
#include <math.h>
#include <stdint.h>

using namespace nvcuda;

#define BATCH 4
#define SEQ 4096
#define DMODEL 1024
#define DK 256
#define MROWS (BATCH * SEQ)

// bf16 hi/lo splits of projections (all row-major [row][d])
__device__ __nv_bfloat16 g_qh[(size_t)MROWS * DK];
__device__ __nv_bfloat16 g_ql[(size_t)MROWS * DK];
__device__ __nv_bfloat16 g_kh[(size_t)MROWS * DK];
__device__ __nv_bfloat16 g_kl[(size_t)MROWS * DK];
__device__ __nv_bfloat16 g_vh[(size_t)MROWS * DK];
__device__ __nv_bfloat16 g_vl[(size_t)MROWS * DK];

// ---------------- projection GEMM (fp32 SIMT, epilogue -> bf16 hi/lo) ----------------
#define PBM 64
#define PBN 64
#define PBK 16

__global__ __launch_bounds__(256) void proj_kernel(
    const float* __restrict__ Xq, const float* __restrict__ Xk, const float* __restrict__ Xv,
    const float* __restrict__ Wq, const float* __restrict__ bq,
    const float* __restrict__ Wk, const float* __restrict__ bk,
    const float* __restrict__ Wv, const float* __restrict__ bv)
{
    const float* X; const float* W; const float* bias;
    int z = blockIdx.z;
    if (z == 0)      { X = Xq; W = Wq; bias = bq; }
    else if (z == 1) { X = Xk; W = Wk; bias = bk; }
    else             { X = Xv; W = Wv; bias = bv; }

    __shared__ float As[PBK][65];
    __shared__ float Bs[PBK][65];

    int tid = threadIdx.x;
    int tx = tid & 15, ty = tid >> 4;
    int m0 = blockIdx.y * PBM, n0 = blockIdx.x * PBN;
    int lrow = tid >> 2, lc = (tid & 3) << 2;

    const float* Xp = X + (size_t)(m0 + lrow) * DMODEL + lc;
    const float* Wp = W + (size_t)(n0 + lrow) * DMODEL + lc;

    float acc[4][4];
    #pragma unroll
    for (int i = 0; i < 4; i++)
        #pragma unroll
        for (int j = 0; j < 4; j++) acc[i][j] = 0.0f;

    for (int k0 = 0; k0 < DMODEL; k0 += PBK) {
        float4 a4 = *(const float4*)(Xp + k0);
        float4 b4 = *(const float4*)(Wp + k0);
        __syncthreads();
        As[lc + 0][lrow] = a4.x; As[lc + 1][lrow] = a4.y;
        As[lc + 2][lrow] = a4.z; As[lc + 3][lrow] = a4.w;
        Bs[lc + 0][lrow] = b4.x; Bs[lc + 1][lrow] = b4.y;
        Bs[lc + 2][lrow] = b4.z; Bs[lc + 3][lrow] = b4.w;
        __syncthreads();
        #pragma unroll
        for (int k = 0; k < PBK; k++) {
            float a[4], b[4];
            #pragma unroll
            for (int i = 0; i < 4; i++) a[i] = As[k][ty + 16 * i];
            #pragma unroll
            for (int j = 0; j < 4; j++) b[j] = Bs[k][tx + 16 * j];
            #pragma unroll
            for (int i = 0; i < 4; i++)
                #pragma unroll
                for (int j = 0; j < 4; j++)
                    acc[i][j] += a[i] * b[j];
        }
    }

    float bb[4];
    #pragma unroll
    for (int j = 0; j < 4; j++) bb[j] = bias[n0 + tx + 16 * j];

    #pragma unroll
    for (int i = 0; i < 4; i++) {
        int mg = m0 + ty + 16 * i;
        #pragma unroll
        for (int j = 0; j < 4; j++) {
            int ng = n0 + tx + 16 * j;
            float x = acc[i][j] + bb[j];
            __nv_bfloat16 h = __float2bfloat16(x);
            __nv_bfloat16 l = __float2bfloat16(x - __bfloat162float(h));
            size_t off = (size_t)mg * DK + ng;
            if (z == 0)      { g_qh[off] = h; g_ql[off] = l; }
            else if (z == 1) { g_kh[off] = h; g_kl[off] = l; }
            else             { g_vh[off] = h; g_vl[off] = l; }
        }
    }
}

// ---------------- wmma bf16 flash attention ----------------
#define BQ 64
#define BKV 64
#define NTILE (SEQ / BKV)
#define LDQ 264           // bf16 ldm for Q/K/V tiles (256 + 8 pad)
#define LDS_ 68           // f32 ldm for S tile
#define LDP 136           // bf16 ldm for P (S buffer reinterpreted)
#define LDO 264           // f32 ldm for O tile

// smem byte offsets
#define SM_QH   0
#define SM_QL   (SM_QH + BQ * LDQ * 2)        //  33792
#define SM_KVH  (SM_QL + BQ * LDQ * 2)        //  67584
#define SM_KVL  (SM_KVH + BKV * LDQ * 2)      // 101376
#define SM_S    (SM_KVL + BKV * LDQ * 2)      // 135168
#define SM_O    (SM_S + BQ * LDS_ * 4)        // 152576
#define SM_TOT  (SM_O + BQ * LDO * 4)         // 220160

// copy [R x 256] bf16 row-major (row stride DK) -> smem ldm=LDQ
__device__ __forceinline__ void copy_tile(__nv_bfloat16* dst, const __nv_bfloat16* src,
                                          int R, int tid)
{
    int total = R * 32;                     // uint4 = 8 bf16
    for (int i = tid; i < total; i += 256) {
        int r = i >> 5, j = i & 31;
        *(uint4*)(dst + r * LDQ + j * 8) = *(const uint4*)(src + (size_t)r * DK + j * 8);
    }
}

__global__ __launch_bounds__(256, 1) void attn_wmma_kernel(float* __restrict__ Out)
{
    extern __shared__ char sm[];
    __nv_bfloat16* Qh = (__nv_bfloat16*)(sm + SM_QH);
    __nv_bfloat16* Ql = (__nv_bfloat16*)(sm + SM_QL);
    __nv_bfloat16* Kh = (__nv_bfloat16*)(sm + SM_KVH);
    __nv_bfloat16* Kl = (__nv_bfloat16*)(sm + SM_KVL);
    float*         Sf = (float*)(sm + SM_S);
    __nv_bfloat16* Pb = (__nv_bfloat16*)(sm + SM_S);   // P overwrites S in place
    float*         Of = (float*)(sm + SM_O);

    int tid = threadIdx.x;
    int w   = tid >> 5;
    int b   = blockIdx.y, q0 = blockIdx.x * BQ;

    // warp tiling: 4 m-strips x 2 n-halves
    int mrow = (w >> 1) * 16;
    int nh   = (w & 1);

    // load persistent Q (hi/lo)
    copy_tile(Qh, g_qh + (size_t)(b * SEQ + q0) * DK, BQ, tid);
    copy_tile(Ql, g_ql + (size_t)(b * SEQ + q0) * DK, BQ, tid);
    // zero O
    for (int i = tid; i < BQ * LDO; i += 256) Of[i] = 0.0f;

    // softmax ownership: 4 threads per row
    int srow = tid >> 2, sq = tid & 3;
    float m_run = -INFINITY, l_run = 0.0f;
    const float SC = 0.0625f;   // 1/sqrt(256)

    for (int it = 0; it < NTILE; it++) {
        int s0 = it * BKV;
        __syncthreads();   // prior PV done -> KV buffer free

        copy_tile(Kh, g_kh + (size_t)(b * SEQ + s0) * DK, BKV, tid);
        copy_tile(Kl, g_kl + (size_t)(b * SEQ + s0) * DK, BKV, tid);
        __syncthreads();

        // ---- S = Q K^T (3-split). B from row-major K via col_major. ----
        {
            wmma::fragment<wmma::accumulator, 16, 16, 16, float> cs[2];
            wmma::fill_fragment(cs[0], 0.0f);
            wmma::fill_fragment(cs[1], 0.0f);
            #pragma unroll
            for (int kc = 0; kc < 16; kc++) {
                wmma::fragment<wmma::matrix_a, 16, 16, 16, __nv_bfloat16, wmma::row_major> ah, al;
                wmma::load_matrix_sync(ah, Qh + mrow * LDQ + kc * 16, LDQ);
                wmma::load_matrix_sync(al, Ql + mrow * LDQ + kc * 16, LDQ);
                #pragma unroll
                for (int j = 0; j < 2; j++) {
                    int n0 = nh * 32 + j * 16;
                    wmma::fragment<wmma::matrix_b, 16, 16, 16, __nv_bfloat16, wmma::col_major> bh, bl;
                    wmma::load_matrix_sync(bh, Kh + n0 * LDQ + kc * 16, LDQ);
                    wmma::load_matrix_sync(bl, Kl + n0 * LDQ + kc * 16, LDQ);
                    wmma::mma_sync(cs[j], ah, bh, cs[j]);
                    wmma::mma_sync(cs[j], ah, bl, cs[j]);
                    wmma::mma_sync(cs[j], al, bh, cs[j]);
                }
            }
            wmma::store_matrix_sync(Sf + mrow * LDS_ + nh * 32,      cs[0], LDS_, wmma::mem_row_major);
            wmma::store_matrix_sync(Sf + mrow * LDS_ + nh * 32 + 16, cs[1], LDS_, wmma::mem_row_major);
        }
        __syncthreads();

        // ---- online softmax: 4 threads per row, 16 cols each ----
        float corr;
        {
            float s[16];
            const float* srp = Sf + srow * LDS_ + sq * 16;
            #pragma unroll
            for (int i = 0; i < 4; i++) {
                float4 v = *(const float4*)(srp + 4 * i);
                s[4*i] = v.x * SC; s[4*i+1] = v.y * SC; s[4*i+2] = v.z * SC; s[4*i+3] = v.w * SC;
            }
            float mt = s[0];
            #pragma unroll
            for (int j = 1; j < 16; j++) mt = fmaxf(mt, s[j]);
            mt = fmaxf(mt, __shfl_xor_sync(0xffffffffu, mt, 1));
            mt = fmaxf(mt, __shfl_xor_sync(0xffffffffu, mt, 2));
            float mnew = fmaxf(m_run, mt);
            corr = __expf(m_run - mnew);
            m_run = mnew;
            float sum = 0.0f;
            #pragma unroll
            for (int j = 0; j < 16; j++) { s[j] = __expf(s[j] - mnew); sum += s[j]; }
            sum += __shfl_xor_sync(0xffffffffu, sum, 1);
            sum += __shfl_xor_sync(0xffffffffu, sum, 2);
            l_run = l_run * corr + sum;

            // pack P hi/lo and overwrite S row in place (all reads of row done)
            uint32_t hw[4], lw[4];
            #pragma unroll
            for (int g = 0; g < 4; g++) {
                float a = s[2*g*2]; // placeholder avoided; compute directly below
            }
            #pragma unroll
            for (int g = 0; g < 4; g++) {
                __nv_bfloat16 h0 = __float2bfloat16(s[4*g+0]);
                __nv_bfloat16 h1 = __float2bfloat16(s[4*g+1]);
                __nv_bfloat16 h2 = __float2bfloat16(s[4*g+2]);
                __nv_bfloat16 h3 = __float2bfloat16(s[4*g+3]);
                __nv_bfloat16 l0 = __float2bfloat16(s[4*g+0] - __bfloat162float(h0));
                __nv_bfloat16 l1 = __float2bfloat16(s[4*g+1] - __bfloat162float(h1));
                __nv_bfloat16 l2 = __float2bfloat16(s[4*g+2] - __bfloat162float(h2));
                __nv_bfloat16 l3 = __float2bfloat16(s[4*g+3] - __bfloat162float(h3));
                __nv_bfloat162 hv01 = __halves2bfloat162(h0, h1), hv23 = __halves2bfloat162(h2, h3);
                __nv_bfloat162 lv01 = __halves2bfloat162(l0, l1), lv23 = __halves2bfloat162(l2, l3);
                hw[g] = (g & 1) ? *(uint32_t*)&hv23 : *(uint32_t*)&hv01;
                // pack properly: two uint32 per 4 values
                hw[g] = 0; // overwritten below
            }
            // straightforward packing: 16 hi bf16 -> 8 uint32 -> 2 uint4
            uint32_t hp[8], lp[8];
            #pragma unroll
            for (int g = 0; g < 8; g++) {
                __nv_bfloat16 ha = __float2bfloat16(s[2*g]);
                __nv_bfloat16 hb = __float2bfloat16(s[2*g+1]);
                __nv_bfloat16 la = __float2bfloat16(s[2*g]   - __bfloat162float(ha));
                __nv_bfloat16 lb = __float2bfloat16(s[2*g+1] - __bfloat162float(hb));
                __nv_bfloat162 hv = __halves2bfloat162(ha, hb);
                __nv_bfloat162 lv = __halves2bfloat162(la, lb);
                hp[g] = *(uint32_t*)&hv;
                lp[g] = *(uint32_t*)&lv;
            }
            __syncwarp();
            __nv_bfloat16* prow = Pb + srow * LDP;
            *(uint4*)(prow + sq * 16)      = make_uint4(hp[0], hp[1], hp[2], hp[3]);
            *(uint4*)(prow + sq * 16 + 8)  = make_uint4(hp[4], hp[5], hp[6], hp[7]);
            *(uint4*)(prow + 64 + sq * 16)     = make_uint4(lp[0], lp[1], lp[2], lp[3]);
            *(uint4*)(prow + 64 + sq * 16 + 8) = make_uint4(lp[4], lp[5], lp[6], lp[7]);
        }

        // block-wide: does any row need O rescale?  (also orders P writes)
        int needR = __syncthreads_or(corr < 1.0f);
        if (needR) {
            float* orow = Of + srow * LDO + sq * 64;
            #pragma unroll
            for (int i = 0; i < 16; i++) {
                float4 v = *(float4*)(orow + 4 * i);
                v.x *= corr; v.y *= corr; v.z *= corr; v.w *= corr;
                *(float4*)(orow + 4 * i) = v;
            }
        }

        // load V tile into KV buffer (K fully consumed by S phase)
        copy_tile(Kh, g_vh + (size_t)(b * SEQ + s0) * DK, BKV, tid);
        copy_tile(Kl, g_vl + (size_t)(b * SEQ + s0) * DK, BKV, tid);
        __syncthreads();

        // ---- O += P V (3-split). A=P row-major, B=V row-major. ----
        {
            int nbase = nh * 128;
            wmma::fragment<wmma::accumulator, 16, 16, 16, float> co[8];
            #pragma unroll
            for (int j = 0; j < 8; j++)
                wmma::load_matrix_sync(co[j], Of + mrow * LDO + nbase + j * 16, LDO, wmma::mem_row_major);
            #pragma unroll
            for (int kc = 0; kc < 4; kc++) {
                wmma::fragment<wmma::matrix_a, 16, 16, 16, __nv_bfloat16, wmma::row_major> pah, pal;
                wmma::load_matrix_sync(pah, Pb + mrow * LDP + kc * 16, LDP);
                wmma::load_matrix_sync(pal, Pb + mrow * LDP + 64 + kc * 16, LDP);
                #pragma unroll
                for (int j = 0; j < 8; j++) {
                    wmma::fragment<wmma::matrix_b, 16, 16, 16, __nv_bfloat16, wmma::row_major> vbh, vbl;
                    wmma::load_matrix_sync(vbh, Kh + (kc * 16) * LDQ + nbase + j * 16, LDQ);
                    wmma::load_matrix_sync(vbl, Kl + (kc * 16) * LDQ + nbase + j * 16, LDQ);
                    wmma::mma_sync(co[j], pah, vbh, co[j]);
                    wmma::mma_sync(co[j], pah, vbl, co[j]);
                    wmma::mma_sync(co[j], pal, vbh, co[j]);
                }
            }
            #pragma unroll
            for (int j = 0; j < 8; j++)
                wmma::store_matrix_sync(Of + mrow * LDO + nbase + j * 16, co[j], LDO, wmma::mem_row_major);
        }
    }
    __syncthreads();

    // ---- epilogue: normalize and write out ----
    {
        float invl = 1.0f / l_run;
        float* orow = Of + srow * LDO + sq * 64;
        float* grow = Out + ((size_t)b * SEQ + q0 + srow) * DK + sq * 64;
        #pragma unroll
        for (int i = 0; i < 16; i++) {
            float4 v = *(float4*)(orow + 4 * i);
            v.x *= invl; v.y *= invl; v.z *= invl; v.w *= invl;
            *(float4*)(grow + 4 * i) = v;
        }
    }
}

// ---------------- launch ----------------
extern "C" void kernel_launch(void* const* d_in, const int* in_sizes, int n_in,
                              void* d_out, int out_size)
{
    const float* xq = (const float*)d_in[0];
    const float* xk = (const float*)d_in[1];
    const float* xv = (const float*)d_in[2];
    const float* Wq = (const float*)d_in[4];
    const float* bq = (const float*)d_in[5];
    const float* Wk = (const float*)d_in[6];
    const float* bk = (const float*)d_in[7];
    const float* Wv = (const float*)d_in[8];
    const float* bv = (const float*)d_in[9];
    float* out = (float*)d_out;

    cudaFuncSetAttribute(attn_wmma_kernel, cudaFuncAttributeMaxDynamicSharedMemorySize, SM_TOT);

    dim3 pg(DK / PBN, MROWS / PBM, 3);
    proj_kernel<<<pg, 256>>>(xq, xk, xv, Wq, bq, Wk, bk, Wv, bv);

    dim3 ag(SEQ / BQ, BATCH);
    attn_wmma_kernel<<<ag, 256, SM_TOT>>>(out);
}